// round 6
// baseline (speedup 1.0000x reference)
#include <cuda_runtime.h>
#include <cuda_bf16.h>
#include <cstdint>

// word2vec negative-sampling loss:
//   second_emb  [200000, 128] f32
//   context_emb [200000, 128] f32
//   v_i, v_j    [131072] i32
//   negsamples  [5, 131072] i32
// out: scalar f32 = -mean_b( logsig(vi.vj) + sum_k logsig(-vi.neg_k) )
//
// Single kernel. NO __threadfence (gpu-scope fence = CCTL.IVALL = full L1D
// flush on sm_103a; measured -8..-15us in R2/R3). Cross-block ordering is
// done with a RELEASE-scoped ticket atomic (orders the partial store to L2
// without touching anyone's L1), and the last block reads partials with
// __ldcg (L2-only) so no acquire/L1-invalidate is needed either.

#define EMBED 128
#define NUM_NEG 5
#define TPB 512
#define WPB 16                      // warps per block
#define NPART 8192                  // batch / WPB for batch=131072

__device__ float        g_partials[NPART];
__device__ unsigned int g_ticket = 0;

__device__ __forceinline__ float fast_log_sigmoid(float x) {
    // logsig(x) = min(x,0) - log(1 + exp(-|x|))
    return fminf(x, 0.0f) - __logf(1.0f + __expf(-fabsf(x)));
}

__device__ __forceinline__ float dot4(float4 a, float4 b) {
    return fmaf(a.x, b.x, fmaf(a.y, b.y, fmaf(a.z, b.z, a.w * b.w)));
}

__global__ void __launch_bounds__(TPB)
w2v_fused(const float* __restrict__ second_emb,
          const float* __restrict__ context_emb,
          const int* __restrict__ v_i,
          const int* __restrict__ v_j,
          const int* __restrict__ negs,
          int batch, float inv_batch,
          float* __restrict__ out)
{
    const int lane = threadIdx.x & 31;
    const int wid  = threadIdx.x >> 5;
    const int e    = blockIdx.x * WPB + wid;    // one element per warp

    float elem_loss = 0.0f;   // valid on lane 0

    if (e < batch) {
        // ---- lane-distributed index gather: ONE LDG for all 7 indices ----
        int myidx = 0;
        if (lane < 7) {
            const int* p;
            if (lane == 0)      p = v_i + e;
            else if (lane == 1) p = v_j + e;
            else                p = negs + (lane - 2) * batch + e;
            myidx = __ldg(p);
        }
        const int ivi = __shfl_sync(0xFFFFFFFFu, myidx, 0);
        const int ivj = __shfl_sync(0xFFFFFFFFu, myidx, 1);
        int ineg[NUM_NEG];
        #pragma unroll
        for (int k = 0; k < NUM_NEG; k++)
            ineg[k] = __shfl_sync(0xFFFFFFFFu, myidx, k + 2);

        // 32-bit row offsets (200000*128 < 2^31)
        const float4* vi_row = reinterpret_cast<const float4*>(
            second_emb + (unsigned)ivi * EMBED);
        float4 a = __ldg(&vi_row[lane]);

        // all 6 context rows issued before consumption (MLP)
        float4 r[NUM_NEG + 1];
        const float4* vj_row = reinterpret_cast<const float4*>(
            context_emb + (unsigned)ivj * EMBED);
        r[0] = __ldg(&vj_row[lane]);
        #pragma unroll
        for (int k = 0; k < NUM_NEG; k++) {
            const float4* nrow = reinterpret_cast<const float4*>(
                context_emb + (unsigned)ineg[k] * EMBED);
            r[k + 1] = __ldg(&nrow[lane]);
        }

        float d[NUM_NEG + 1];
        #pragma unroll
        for (int j = 0; j < NUM_NEG + 1; j++)
            d[j] = dot4(a, r[j]);

        // split-butterfly: fold halves once, then each half-warp finishes
        // 3 of the 6 dot reductions (21 shuffles instead of 30)
        #pragma unroll
        for (int j = 0; j < 6; j++)
            d[j] += __shfl_xor_sync(0xFFFFFFFFu, d[j], 16);

        const bool hi = lane >= 16;
        float v0 = hi ? d[3] : d[0];
        float v1 = hi ? d[4] : d[1];
        float v2 = hi ? d[5] : d[2];

        #pragma unroll
        for (int off = 8; off > 0; off >>= 1) {
            v0 += __shfl_xor_sync(0xFFFFFFFFu, v0, off);
            v1 += __shfl_xor_sync(0xFFFFFFFFu, v1, off);
            v2 += __shfl_xor_sync(0xFFFFFFFFu, v2, off);
        }
        // low half lanes hold D0,D1,D2; high half D3,D4,D5 (replicated)

        // distributed logsig: lanes {0,1,2,16,17,18} each own one term
        const int sl = lane & 15;
        float x = v0;
        x = (sl == 1) ? v1 : x;
        x = (sl == 2) ? v2 : x;
        float arg = (lane == 0) ? x : -x;      // positive term only for D0
        float t = fast_log_sigmoid(arg);
        t = (sl < 3) ? t : 0.0f;

        t += __shfl_xor_sync(0xFFFFFFFFu, t, 16);
        t += __shfl_xor_sync(0xFFFFFFFFu, t, 1);
        t += __shfl_xor_sync(0xFFFFFFFFu, t, 2);
        elem_loss = t;                          // lane 0 holds element loss
    }

    // ---- block reduce (deterministic): 16 warp values -> 1 partial ----
    __shared__ float ws[WPB];
    if (lane == 0)
        ws[wid] = elem_loss;
    __syncthreads();

    __shared__ int isLast;
    if (threadIdx.x < 32) {
        float s = (threadIdx.x < WPB) ? ws[threadIdx.x] : 0.0f;
        #pragma unroll
        for (int off = 8; off > 0; off >>= 1)
            s += __shfl_xor_sync(0xFFFFFFFFu, s, off);
        if (threadIdx.x == 0) {
            g_partials[blockIdx.x] = s;
            // release-scoped ticket: orders the partial store to L2
            // WITHOUT a CCTL.IVALL L1 flush (unlike __threadfence()).
            unsigned int old;
            asm volatile("atom.release.gpu.add.u32 %0, [%1], 1;"
                         : "=r"(old) : "l"(&g_ticket) : "memory");
            isLast = (old == (unsigned int)(gridDim.x - 1));
            if (isLast)
                g_ticket = 0;   // reset for next graph replay
        }
    }
    __syncthreads();

    // ---- last-arriving block folds all partials (fixed order -> exact) ----
    if (isLast) {
        // 8192 partials = 2048 float4; 512 threads x 4 independent float4.
        // __ldcg: read straight from L2 (coherence point) — partials were
        // release-ordered there; our own L1 never cached these lines anyway.
        const float4* p = reinterpret_cast<const float4*>(g_partials);
        const int tid = threadIdx.x;
        float4 s4 = make_float4(0.f, 0.f, 0.f, 0.f);
        #pragma unroll
        for (int i = 0; i < 4; i++) {
            float4 v = __ldcg(&p[tid + i * TPB]);
            s4.x += v.x; s4.y += v.y; s4.z += v.z; s4.w += v.w;
        }
        float s = (s4.x + s4.y) + (s4.z + s4.w);

        #pragma unroll
        for (int off = 16; off > 0; off >>= 1)
            s += __shfl_xor_sync(0xFFFFFFFFu, s, off);

        __shared__ float fs[WPB];
        if (lane == 0)
            fs[wid] = s;
        __syncthreads();

        if (threadIdx.x < 32) {
            float tot = (threadIdx.x < WPB) ? fs[threadIdx.x] : 0.0f;
            #pragma unroll
            for (int off = 8; off > 0; off >>= 1)
                tot += __shfl_xor_sync(0xFFFFFFFFu, tot, off);
            if (threadIdx.x == 0)
                out[0] = -tot * inv_batch;
        }
    }
}

extern "C" void kernel_launch(void* const* d_in, const int* in_sizes, int n_in,
                              void* d_out, int out_size)
{
    const float* second_emb  = (const float*)d_in[0];
    const float* context_emb = (const float*)d_in[1];
    const int*   v_i         = (const int*)d_in[2];
    const int*   v_j         = (const int*)d_in[3];
    const int*   negs        = (const int*)d_in[4];

    const int batch  = in_sizes[2];                 // 131072
    const int blocks = (batch + WPB - 1) / WPB;     // 8192

    w2v_fused<<<blocks, TPB>>>(second_emb, context_emb, v_i, v_j, negs,
                               batch, 1.0f / (float)batch, (float*)d_out);
}

// round 8
// speedup vs baseline: 1.2259x; 1.2259x over previous
#include <cuda_runtime.h>
#include <cuda_bf16.h>
#include <cstdint>

// word2vec negative-sampling loss:
//   second_emb  [200000, 128] f32   (~0.65 expected uses/row -> streaming)
//   context_emb [200000, 128] f32   (~3.9 expected uses/row  -> L2-resident)
//   v_i, v_j    [131072] i32
//   negsamples  [5, 131072] i32
// out: scalar f32 = -mean_b( logsig(vi.vj) + sum_k logsig(-vi.neg_k) )
//
// Two kernels (all 3 single-kernel fusion attempts regressed: fence/atomic
// protocol costs >> 4.6us second launch). L2 eviction-priority steering via
// createpolicy + ld.global.nc.L2::cache_hint (the inline .L2::evict_*
// qualifier is rejected by ptxas for .v4.f32 on sm_103).

#define EMBED 128
#define NUM_NEG 5
#define TPB 512
#define WPB 16                      // warps per block
#define NPART 8192                  // batch / WPB for batch=131072

__device__ float g_partials[NPART];

__device__ __forceinline__ float fast_log_sigmoid(float x) {
    // logsig(x) = min(x,0) - log(1 + exp(-|x|))
    return fminf(x, 0.0f) - __logf(1.0f + __expf(-fabsf(x)));
}

__device__ __forceinline__ float dot4(float4 a, float4 b) {
    return fmaf(a.x, b.x, fmaf(a.y, b.y, fmaf(a.z, b.z, a.w * b.w)));
}

__device__ __forceinline__ uint64_t mk_policy_evict_first() {
    uint64_t p;
    asm("createpolicy.fractional.L2::evict_first.b64 %0, 1.0;" : "=l"(p));
    return p;
}

__device__ __forceinline__ uint64_t mk_policy_evict_last() {
    uint64_t p;
    asm("createpolicy.fractional.L2::evict_last.b64 %0, 1.0;" : "=l"(p));
    return p;
}

__device__ __forceinline__ float4 ldg_hint(const float4* p, uint64_t policy) {
    float4 v;
    asm volatile("ld.global.nc.L2::cache_hint.v4.f32 {%0,%1,%2,%3}, [%4], %5;"
                 : "=f"(v.x), "=f"(v.y), "=f"(v.z), "=f"(v.w)
                 : "l"(p), "l"(policy));
    return v;
}

__global__ void __launch_bounds__(TPB)
w2v_main(const float* __restrict__ second_emb,
         const float* __restrict__ context_emb,
         const int* __restrict__ v_i,
         const int* __restrict__ v_j,
         const int* __restrict__ negs,
         int batch)
{
    const int lane = threadIdx.x & 31;
    const int wid  = threadIdx.x >> 5;
    const int e    = blockIdx.x * WPB + wid;    // one element per warp

    float elem_loss = 0.0f;   // valid on lane 0

    if (e < batch) {
        const uint64_t pol_stream   = mk_policy_evict_first();
        const uint64_t pol_resident = mk_policy_evict_last();

        // ---- lane-distributed index gather: ONE LDG for all 7 indices ----
        int myidx = 0;
        if (lane < 7) {
            const int* p;
            if (lane == 0)      p = v_i + e;
            else if (lane == 1) p = v_j + e;
            else                p = negs + (lane - 2) * batch + e;
            myidx = __ldg(p);
        }
        const int ivi = __shfl_sync(0xFFFFFFFFu, myidx, 0);
        const int ivj = __shfl_sync(0xFFFFFFFFu, myidx, 1);
        int ineg[NUM_NEG];
        #pragma unroll
        for (int k = 0; k < NUM_NEG; k++)
            ineg[k] = __shfl_sync(0xFFFFFFFFu, myidx, k + 2);

        // 32-bit row offsets (200000*128 < 2^31)
        const float4* vi_row = reinterpret_cast<const float4*>(
            second_emb + (unsigned)ivi * EMBED);
        float4 a = ldg_hint(&vi_row[lane], pol_stream);

        // all 6 context rows issued before consumption (MLP)
        float4 r[NUM_NEG + 1];
        const float4* vj_row = reinterpret_cast<const float4*>(
            context_emb + (unsigned)ivj * EMBED);
        r[0] = ldg_hint(&vj_row[lane], pol_resident);
        #pragma unroll
        for (int k = 0; k < NUM_NEG; k++) {
            const float4* nrow = reinterpret_cast<const float4*>(
                context_emb + (unsigned)ineg[k] * EMBED);
            r[k + 1] = ldg_hint(&nrow[lane], pol_resident);
        }

        float d[NUM_NEG + 1];
        #pragma unroll
        for (int j = 0; j < NUM_NEG + 1; j++)
            d[j] = dot4(a, r[j]);

        // split-butterfly: fold halves once, then each half-warp finishes
        // 3 of the 6 dot reductions (21 shuffles instead of 30)
        #pragma unroll
        for (int j = 0; j < 6; j++)
            d[j] += __shfl_xor_sync(0xFFFFFFFFu, d[j], 16);

        const bool hi = lane >= 16;
        float v0 = hi ? d[3] : d[0];
        float v1 = hi ? d[4] : d[1];
        float v2 = hi ? d[5] : d[2];

        #pragma unroll
        for (int off = 8; off > 0; off >>= 1) {
            v0 += __shfl_xor_sync(0xFFFFFFFFu, v0, off);
            v1 += __shfl_xor_sync(0xFFFFFFFFu, v1, off);
            v2 += __shfl_xor_sync(0xFFFFFFFFu, v2, off);
        }
        // low half lanes hold D0,D1,D2; high half D3,D4,D5 (replicated)

        // distributed logsig: lanes {0,1,2,16,17,18} each own one term
        const int sl = lane & 15;
        float x = v0;
        x = (sl == 1) ? v1 : x;
        x = (sl == 2) ? v2 : x;
        float arg = (lane == 0) ? x : -x;      // positive term only for D0
        float t = fast_log_sigmoid(arg);
        t = (sl < 3) ? t : 0.0f;

        t += __shfl_xor_sync(0xFFFFFFFFu, t, 16);
        t += __shfl_xor_sync(0xFFFFFFFFu, t, 1);
        t += __shfl_xor_sync(0xFFFFFFFFu, t, 2);
        elem_loss = t;                          // lane 0 holds element loss
    }

    // block reduce (deterministic): 16 warp values -> 1 partial
    __shared__ float ws[WPB];
    if (lane == 0)
        ws[wid] = elem_loss;
    __syncthreads();

    if (threadIdx.x < 32) {
        float s = (threadIdx.x < WPB) ? ws[threadIdx.x] : 0.0f;
        #pragma unroll
        for (int off = 8; off > 0; off >>= 1)
            s += __shfl_xor_sync(0xFFFFFFFFu, s, off);
        if (threadIdx.x == 0)
            g_partials[blockIdx.x] = s;
    }
}

__global__ void __launch_bounds__(1024)
w2v_reduce(float* __restrict__ out, float inv_batch)
{
    // 8192 partials = 2048 float4; 1024 threads x 2 independent float4 each
    const float4* p = reinterpret_cast<const float4*>(g_partials);
    const int tid = threadIdx.x;

    float4 u = __ldg(&p[tid]);
    float4 v = __ldg(&p[tid + 1024]);
    float s = ((u.x + u.y) + (u.z + u.w)) + ((v.x + v.y) + (v.z + v.w));

    #pragma unroll
    for (int off = 16; off > 0; off >>= 1)
        s += __shfl_xor_sync(0xFFFFFFFFu, s, off);

    __shared__ float sh[32];
    if ((tid & 31) == 0)
        sh[tid >> 5] = s;
    __syncthreads();

    if (tid < 32) {
        float t = sh[tid];
        #pragma unroll
        for (int off = 16; off > 0; off >>= 1)
            t += __shfl_xor_sync(0xFFFFFFFFu, t, off);
        if (tid == 0)
            out[0] = -t * inv_batch;
    }
}

extern "C" void kernel_launch(void* const* d_in, const int* in_sizes, int n_in,
                              void* d_out, int out_size)
{
    const float* second_emb  = (const float*)d_in[0];
    const float* context_emb = (const float*)d_in[1];
    const int*   v_i         = (const int*)d_in[2];
    const int*   v_j         = (const int*)d_in[3];
    const int*   negs        = (const int*)d_in[4];

    const int batch  = in_sizes[2];                 // 131072
    const int blocks = (batch + WPB - 1) / WPB;     // 8192

    w2v_main<<<blocks, TPB>>>(second_emb, context_emb, v_i, v_j, negs, batch);
    w2v_reduce<<<1, 1024>>>((float*)d_out, 1.0f / (float)batch);
}